// round 13
// baseline (speedup 1.0000x reference)
#include <cuda_runtime.h>
#include <cuda_fp16.h>
#include <stdint.h>

#define BB 256
#define TT 512
#define HH 512
#define II 256
#define BH 131072
#define NCTA 128
#define NTHR 256

// CTA tile: m32 x n128. 8 mtiles x 16 ntiles.
// SMEM: A chunk dbl-buf 2 x 16K = 32K, A lo (pre GEMM only) at 32K..48K,
//       U (fp16, n128 x k512, pitch 1024B) at 64K..192K
#define AB1   16384
#define SO_AL 32768
#define SO_U  65536
#define SMEM_TOT 196608

// ---------------- device globals ----------------
__device__ __align__(16) __half g_Uf[2048 * 512];   // permuted U, fp16
__device__ __align__(16) __half g_Wf[2048 * 256];   // permuted W, fp16
__device__ __align__(16) __half g_x0h[256 * 256];
__device__ __align__(16) __half g_x0l[256 * 256];
__device__ __align__(16) __half g_ah[2][BH];        // h stream (fp16, 1-pass)
__device__ __align__(16) unsigned g_flag[128];      // [mtile*16+ntile] = steps produced

// ---------------- helpers ----------------
__device__ __forceinline__ uint32_t smem_u32(const void *p) {
    uint32_t a;
    asm("{ .reg .u64 t; cvta.to.shared.u64 t, %1; cvt.u32.u64 %0, t; }"
        : "=r"(a) : "l"(p));
    return a;
}
__device__ __forceinline__ void cpa16(uint32_t dst, const void *src) {
    asm volatile("cp.async.cg.shared.global [%0], [%1], 16;"
                 :: "r"(dst), "l"(__cvta_generic_to_global(src)) : "memory");
}
#define CP_COMMIT asm volatile("cp.async.commit_group;" ::: "memory")

__device__ __forceinline__ unsigned ldrlx(const unsigned *p) {
    unsigned v;
    asm volatile("ld.relaxed.gpu.global.u32 %0, [%1];"
                 : "=r"(v) : "l"(__cvta_generic_to_global((void *)p)) : "memory");
    return v;
}
// Wait until the 8 flags at f[0..8) are all >= need. 8 independent relaxed
// loads per trip (pipelined, ~1 L2 RTT) + one fence on exit (acquire role).
__device__ __forceinline__ void wait8(const unsigned *f, unsigned need) {
    for (;;) {
        unsigned m0 = ldrlx(f + 0), m1 = ldrlx(f + 1);
        unsigned m2 = ldrlx(f + 2), m3 = ldrlx(f + 3);
        unsigned m4 = ldrlx(f + 4), m5 = ldrlx(f + 5);
        unsigned m6 = ldrlx(f + 6), m7 = ldrlx(f + 7);
        unsigned mn = min(min(min(m0, m1), min(m2, m3)),
                          min(min(m4, m5), min(m6, m7)));
        if (mn >= need) break;
    }
    __threadfence();
}
__device__ __forceinline__ void ldsm4(uint32_t addr, uint32_t r[4]) {
    asm volatile("ldmatrix.sync.aligned.m8n8.x4.shared.b16 {%0,%1,%2,%3}, [%4];"
                 : "=r"(r[0]), "=r"(r[1]), "=r"(r[2]), "=r"(r[3]) : "r"(addr));
}
__device__ __forceinline__ void mmaf16(float c[4], const uint32_t a[4],
                                       uint32_t b0, uint32_t b1) {
    asm volatile(
        "mma.sync.aligned.m16n8k16.row.col.f32.f16.f16.f32 "
        "{%0,%1,%2,%3}, {%4,%5,%6,%7}, {%8,%9}, {%0,%1,%2,%3};"
        : "+f"(c[0]), "+f"(c[1]), "+f"(c[2]), "+f"(c[3])
        : "r"(a[0]), "r"(a[1]), "r"(a[2]), "r"(a[3]), "r"(b0), "r"(b1));
}
__device__ __forceinline__ float sigf(float x) {
    return __fdividef(1.0f, 1.0f + __expf(-x));
}
__device__ __forceinline__ float tanhfast(float x) {
    return 1.0f - __fdividef(2.0f, __expf(2.0f * x) + 1.0f);
}

// ---------------- prep: permute cols (gate-interleave) + fp16 convert/split ----------
__global__ void prep_kernel(const float *__restrict__ rnn,
                            const float *__restrict__ h0,
                            const float *__restrict__ Ww,
                            const float *__restrict__ Uw)
{
    if (blockIdx.x == 0 && threadIdx.x < 128)
        g_flag[threadIdx.x] = 0u;
    const long TU = 512L * 2048, TW = 256L * 2048, TX = 256L * 256, TH = 256L * 512;
    const long TOT = TU + TW + TX + TH;
    for (long i = (long)blockIdx.x * blockDim.x + threadIdx.x; i < TOT;
         i += (long)gridDim.x * blockDim.x) {
        if (i < TU) {
            long k = i >> 11;
            int n = (int)(i & 2047);
            int p = ((n & 511) << 2) | (n >> 9);   // h*4 + gate
            g_Uf[(long)p * 512 + k] = __float2half_rn(Uw[i]);
        } else if (i < TU + TW) {
            long j = i - TU;
            long k = j >> 11;
            int n = (int)(j & 2047);
            int p = ((n & 511) << 2) | (n >> 9);
            g_Wf[(long)p * 256 + k] = __float2half_rn(Ww[j]);
        } else if (i < TU + TW + TX) {
            long j = i - TU - TW;
            float v = rnn[j];
            __half hi = __float2half_rn(v);
            g_x0h[j] = hi;
            g_x0l[j] = __float2half_rn(v - __half2float(hi));
        } else {
            long j = i - TU - TW - TX;
            g_ah[0][j] = __float2half_rn(h0[j]);
        }
    }
}

// ---------------- A chunk fill: 32 rows x 256 k fp16 into chunk buffer ----------------
__device__ __forceinline__ void fill_chunk(const __half *__restrict__ gh, int ldk,
                                           int m0, int c, uint32_t smb, int tid)
{
#pragma unroll
    for (int i = 0; i < 4; ++i) {
        int u = tid + 256 * i, m = u >> 5, kg = u & 31;
        size_t go = (size_t)(m0 + m) * ldk + c * 256 + kg * 8;
        uint32_t d = (uint32_t)((c & 1) * AB1 + m * 512 + ((kg * 16) ^ ((m & 7) << 4)));
        cpa16(smb + d, gh + go);
    }
}

// ---------------- compute one K256 chunk ----------------
template <int BPITCH>
__device__ __forceinline__ void compute_chunk(uint32_t ab, uint32_t smb, int kc,
                                              int lane, int wm, int wn, float C[4][4])
{
#pragma unroll
    for (int sub = 0; sub < 16; ++sub) {
        uint32_t ahr[4];
        {
            int mat = lane >> 3, rr = lane & 7;
            int mloc = wm * 16 + ((mat & 1) << 3) + rr;
            int kb = sub * 32 + ((mat >> 1) << 4);
            uint32_t off = mloc * 512 + (kb ^ ((mloc & 7) << 4));
            ldsm4(ab + off, ahr);
        }
        uint32_t bf[8];
        const int kg2 = (kc * 256 + sub * 16) * 2;
#pragma unroll
        for (int half = 0; half < 2; ++half) {
            int mat = lane >> 3, rr = lane & 7;
            int nloc = wn * 32 + half * 16 + ((mat >> 1) << 3) + rr;
            int kb = kg2 + ((mat & 1) << 4);
            uint32_t off = nloc * BPITCH + (kb ^ ((nloc & 7) << 4));
            ldsm4(smb + SO_U + off, &bf[half * 4]);
        }
#pragma unroll
        for (int nb = 0; nb < 4; ++nb)
            mmaf16(C[nb], ahr, bf[nb * 2], bf[nb * 2 + 1]);
    }
}

// ---------------- pre GEMM: 2-pass split fp16 (x0), K=256 single chunk -------------
__device__ __forceinline__ void run_pre(
    const __half *__restrict__ gh, const __half *__restrict__ gl,
    int m0, uint32_t smb, int tid, int lane, int wm, int wn, float C[4][4])
{
#pragma unroll
    for (int i = 0; i < 4; ++i) {
        int u = tid + 256 * i, m = u >> 5, kg = u & 31;
        size_t go = (size_t)(m0 + m) * II + kg * 8;
        uint32_t d = (uint32_t)(m * 512 + ((kg * 16) ^ ((m & 7) << 4)));
        cpa16(smb + d, gh + go);
        cpa16(smb + d + SO_AL, gl + go);
    }
    CP_COMMIT;
    asm volatile("cp.async.wait_group 0;" ::: "memory");
    __syncthreads();
#pragma unroll
    for (int sub = 0; sub < 16; ++sub) {
        uint32_t ahr[4], alr[4];
        {
            int mat = lane >> 3, rr = lane & 7;
            int mloc = wm * 16 + ((mat & 1) << 3) + rr;
            int kb = sub * 32 + ((mat >> 1) << 4);
            uint32_t off = mloc * 512 + (kb ^ ((mloc & 7) << 4));
            ldsm4(smb + off, ahr);
            ldsm4(smb + SO_AL + off, alr);
        }
        uint32_t bf[8];
        const int kg2 = (sub * 16) * 2;
#pragma unroll
        for (int half = 0; half < 2; ++half) {
            int mat = lane >> 3, rr = lane & 7;
            int nloc = wn * 32 + half * 16 + ((mat >> 1) << 3) + rr;
            int kb = kg2 + ((mat & 1) << 4);
            uint32_t off = nloc * 512 + (kb ^ ((nloc & 7) << 4));
            ldsm4(smb + SO_U + off, &bf[half * 4]);
        }
#pragma unroll
        for (int nb = 0; nb < 4; ++nb) {
            mmaf16(C[nb], ahr, bf[nb * 2], bf[nb * 2 + 1]);
            mmaf16(C[nb], alr, bf[nb * 2], bf[nb * 2 + 1]);
        }
    }
}

// ---------------- main persistent kernel ----------------
__global__ void __launch_bounds__(NTHR, 1) lstm_mma(
    const int *__restrict__ bsz, const float *__restrict__ h0in,
    const float *__restrict__ c0in, const float *__restrict__ taup,
    const float *__restrict__ Wb, float *__restrict__ out)
{
    extern __shared__ char sm[];
    const uint32_t smb = smem_u32(sm);
    const int tid = threadIdx.x, cta = blockIdx.x;
    const int lane = tid & 31, wid = tid >> 5;
    const int wm = wid & 1, wn = wid >> 1;           // 2m x 4n warps (m16n32)
    const int mtile = cta & 7, ntile = cta >> 3;     // 8 mtiles x 16 ntiles
    const int m0 = mtile * 32;
    const float tauv = __ldg(taup);
    const unsigned *fb = &g_flag[mtile * 16];

    const int cc = lane & 3;
    const int hbash = ntile * 32 + wn * 8 + (cc >> 1);
    const int mg0 = m0 + wm * 16 + (lane >> 2);

    // ---- fill W slice (n128 x k256, pitch 512B) into U slot, compute pre ----
    {
        char *p = sm;
#pragma unroll
        for (int i = 0; i < 16; ++i) {
            int u = tid + 256 * i, n = u >> 5, kg = u & 31;
            uint32_t d = n * 512 + ((kg * 16) ^ ((n & 7) << 4));
            *(uint4 *)(p + SO_U + d) =
                *(const uint4 *)(g_Wf + (size_t)(ntile * 128 + n) * 256 + kg * 8);
        }
    }
    __syncthreads();

    float C[4][4];
#pragma unroll
    for (int a = 0; a < 4; ++a)
#pragma unroll
        for (int r = 0; r < 4; ++r) C[a][r] = 0.0f;
    run_pre(g_x0h, g_x0l, m0, smb, tid, lane, wm, wn, C);

    float pre[4][4];
#pragma unroll
    for (int nb = 0; nb < 4; ++nb)
#pragma unroll
        for (int r = 0; r < 4; ++r) {
            int gate = (cc * 2 + (r & 1)) & 3;
            int hg = ntile * 32 + wn * 8 + nb * 2 + (cc >> 1);
            pre[nb][r] = C[nb][r] + __ldg(Wb + gate * 512 + hg);
        }
    __syncthreads();

    // ---- fill U resident (n128 x k512, pitch 1024B, fp16, 128KB) ----
    {
        char *p = sm;
#pragma unroll
        for (int i = 0; i < 32; ++i) {
            int u = tid + 256 * i, n = u >> 6, kg = u & 63;
            uint32_t d = n * 1024 + ((kg * 16) ^ ((n & 7) << 4));
            *(uint4 *)(p + SO_U + d) =
                *(const uint4 *)(g_Uf + (size_t)(ntile * 128 + n) * 512 + kg * 8);
        }
    }
    __syncthreads();

    // ---- per-thread cell states (4 cells: [p][mh]); fp32 resident all steps ----
    float cs[2][2], hs[2][2];
#pragma unroll
    for (int p = 0; p < 2; ++p) {
        int nb = (lane & 1) ? 2 + p : p;
        int hg = hbash + nb * 2;
#pragma unroll
        for (int mh = 0; mh < 2; ++mh) {
            int mg = mg0 + mh * 8;
            cs[p][mh] = __ldg(c0in + (size_t)mg * 512 + hg);
            hs[p][mh] = __ldg(h0in + (size_t)mg * 512 + hg);
        }
    }

    // ---- time loop: chunk-level producer flags (no monolithic barrier) ----
    for (int t = 0; t < TT; ++t) {
        const __half *gh = g_ah[t & 1];
#pragma unroll
        for (int a = 0; a < 4; ++a)
#pragma unroll
            for (int r = 0; r < 4; ++r) C[a][r] = 0.0f;

        // chunk 0: gated by producers ntile 0..7
        if (tid == 0) wait8(fb, (unsigned)t);
        __syncthreads();                       // flag visibility + A-buf reuse guard
        fill_chunk(gh, HH, m0, 0, smb, tid);
        CP_COMMIT;
        // chunk 1: gated by producers ntile 8..15 (overlaps chunk-0 in flight)
        if (tid == 0) wait8(fb + 8, (unsigned)t);
        __syncthreads();
        fill_chunk(gh, HH, m0, 1, smb, tid);
        CP_COMMIT;

        asm volatile("cp.async.wait_group 1;" ::: "memory");
        __syncthreads();
        compute_chunk<1024>(smb, smb, 0, lane, wm, wn, C);
        asm volatile("cp.async.wait_group 0;" ::: "memory");
        __syncthreads();
        compute_chunk<1024>(smb + AB1, smb, 1, lane, wm, wn, C);

        const int bs = __ldg(bsz + t);

        // gate sums = C + pre; exchange complementary gate pairs with lane^1
        float own[2][4], R[2][4];
#pragma unroll
        for (int p = 0; p < 2; ++p)
#pragma unroll
            for (int r = 0; r < 4; ++r) {
                float lo2 = C[p][r] + pre[p][r];
                float hi2 = C[2 + p][r] + pre[2 + p][r];
                own[p][r] = (lane & 1) ? hi2 : lo2;
                float send = (lane & 1) ? lo2 : hi2;
                R[p][r] = __shfl_xor_sync(0xffffffffu, send, 1);
            }

        float o4[2][2];
#pragma unroll
        for (int p = 0; p < 2; ++p) {
#pragma unroll
            for (int mh = 0; mh < 2; ++mh) {
                float vi, vf, vg, vo;
                if (lane & 1) {
                    vg = own[p][mh * 2]; vo = own[p][mh * 2 + 1];
                    vi = R[p][mh * 2];   vf = R[p][mh * 2 + 1];
                } else {
                    vi = own[p][mh * 2]; vf = own[p][mh * 2 + 1];
                    vg = R[p][mh * 2];   vo = R[p][mh * 2 + 1];
                }
                int mg = mg0 + mh * 8;
                float cn = sigf(vf) * cs[p][mh] + sigf(vi) * tanhfast(vg);
                float hn = sigf(vo) * tanhfast(cn);
                bool act = (mg < bs);
                o4[p][mh] = act ? hn : 0.0f;
                if (act) { cs[p][mh] = cn; hs[p][mh] = hn; }
            }
        }

        if (t < TT - 1) {
            // drift on h dims 0,1 (ntile 0, wn 0, nb 0 → even lanes, cc 0 and 2)
            if (ntile == 0 && wn == 0) {
#pragma unroll
                for (int mh = 0; mh < 2; ++mh) {
                    float mine = hs[0][mh];
                    float oth = __shfl_xor_sync(0xffffffffu, mine, 2);
                    if (!(lane & 1)) {
                        if (cc == 0)
                            hs[0][mh] = mine + tauv * (1.5f * mine + oth * (1.0f / 1.5f));
                        else if (cc == 2)
                            hs[0][mh] = mine - tauv * (1.5f * oth);
                    }
                }
            }
            __half *dh = g_ah[(t + 1) & 1];
#pragma unroll
            for (int p = 0; p < 2; ++p) {
                int nb = (lane & 1) ? 2 + p : p;
                int hg = hbash + nb * 2;
#pragma unroll
                for (int mh = 0; mh < 2; ++mh) {
                    int mg = mg0 + mh * 8;
                    dh[(size_t)mg * 512 + hg] = __float2half_rn(hs[p][mh]);
                }
            }
            // release h writes, publish flag; out-stores overlap with stragglers
            __threadfence();
            __syncthreads();
            if (tid == 0)
                *(volatile unsigned *)&g_flag[mtile * 16 + ntile] = (unsigned)(t + 1);
#pragma unroll
            for (int p = 0; p < 2; ++p) {
                int nb = (lane & 1) ? 2 + p : p;
                int hg = hbash + nb * 2;
#pragma unroll
                for (int mh = 0; mh < 2; ++mh)
                    out[(size_t)t * BH + (size_t)(mg0 + mh * 8) * 512 + hg] = o4[p][mh];
            }
        } else {
#pragma unroll
            for (int p = 0; p < 2; ++p) {
                int nb = (lane & 1) ? 2 + p : p;
                int hg = hbash + nb * 2;
#pragma unroll
                for (int mh = 0; mh < 2; ++mh)
                    out[(size_t)t * BH + (size_t)(mg0 + mh * 8) * 512 + hg] = o4[p][mh];
            }
        }
    }

    // ---- final h, c (from fp32 registers) ----
    const size_t ofs = (size_t)TT * BH;
#pragma unroll
    for (int p = 0; p < 2; ++p) {
        int nb = (lane & 1) ? 2 + p : p;
        int hg = hbash + nb * 2;
#pragma unroll
        for (int mh = 0; mh < 2; ++mh) {
            int mg = mg0 + mh * 8;
            out[ofs + (size_t)mg * 512 + hg] = hs[p][mh];
            out[ofs + BH + (size_t)mg * 512 + hg] = cs[p][mh];
        }
    }
}

extern "C" void kernel_launch(void *const *d_in, const int *in_sizes, int n_in,
                              void *d_out, int out_size)
{
    const float *rnn = (const float *)d_in[0];
    const int *bsz = (const int *)d_in[1];
    const float *h0 = (const float *)d_in[2];
    const float *c0 = (const float *)d_in[3];
    const float *tau = (const float *)d_in[4];
    const float *Ww = (const float *)d_in[5];
    const float *Wb = (const float *)d_in[6];
    const float *Uw = (const float *)d_in[7];
    float *out = (float *)d_out;

    cudaFuncSetAttribute(lstm_mma, cudaFuncAttributeMaxDynamicSharedMemorySize,
                         SMEM_TOT);
    prep_kernel<<<512, 256>>>(rnn, h0, Ww, Uw);
    lstm_mma<<<NCTA, NTHR, SMEM_TOT>>>(bsz, h0, c0, tau, Wb, out);
}

// round 14
// speedup vs baseline: 1.3303x; 1.3303x over previous
#include <cuda_runtime.h>
#include <cuda_fp16.h>
#include <stdint.h>

#define BB 256
#define TT 512
#define HH 512
#define II 256
#define BH 131072
#define NCTA 128
#define NTHR 128

// CTA tile: m32 x n128, 4 warps of m32n32. 8 mtiles x 16 ntiles.
// SMEM: A chunk dbl-buf 2 x 16K = 32K, A lo (pre GEMM only) at 32K..48K,
//       U (fp16, n128 x k512, pitch 1024B) at 64K..192K
#define AB1   16384
#define SO_AL 32768
#define SO_U  65536
#define SMEM_TOT 196608

// ---------------- device globals ----------------
__device__ __align__(16) __half g_Uf[2048 * 512];   // permuted U, fp16
__device__ __align__(16) __half g_Wf[2048 * 256];   // permuted W, fp16
__device__ __align__(16) __half g_x0h[256 * 256];
__device__ __align__(16) __half g_x0l[256 * 256];
__device__ __align__(16) __half g_ah[2][BH];        // h stream (fp16, 1-pass)
__device__ unsigned int g_arrm[8 * 32];             // per-mtile counters, 128B apart

// ---------------- helpers ----------------
__device__ __forceinline__ uint32_t smem_u32(const void *p) {
    uint32_t a;
    asm("{ .reg .u64 t; cvta.to.shared.u64 t, %1; cvt.u32.u64 %0, t; }"
        : "=r"(a) : "l"(p));
    return a;
}
__device__ __forceinline__ void cpa16(uint32_t dst, const void *src) {
    asm volatile("cp.async.cg.shared.global [%0], [%1], 16;"
                 :: "r"(dst), "l"(__cvta_generic_to_global(src)) : "memory");
}
#define CP_COMMIT asm volatile("cp.async.commit_group;" ::: "memory")

__device__ __forceinline__ unsigned ldacq(const unsigned *p) {
    unsigned v;
    asm volatile("ld.acquire.gpu.global.u32 %0, [%1];"
                 : "=r"(v) : "l"(__cvta_generic_to_global((void *)p)) : "memory");
    return v;
}
__device__ __forceinline__ void ldsm4(uint32_t addr, uint32_t r[4]) {
    asm volatile("ldmatrix.sync.aligned.m8n8.x4.shared.b16 {%0,%1,%2,%3}, [%4];"
                 : "=r"(r[0]), "=r"(r[1]), "=r"(r[2]), "=r"(r[3]) : "r"(addr));
}
__device__ __forceinline__ void mmaf16(float c[4], const uint32_t a[4],
                                       uint32_t b0, uint32_t b1) {
    asm volatile(
        "mma.sync.aligned.m16n8k16.row.col.f32.f16.f16.f32 "
        "{%0,%1,%2,%3}, {%4,%5,%6,%7}, {%8,%9}, {%0,%1,%2,%3};"
        : "+f"(c[0]), "+f"(c[1]), "+f"(c[2]), "+f"(c[3])
        : "r"(a[0]), "r"(a[1]), "r"(a[2]), "r"(a[3]), "r"(b0), "r"(b1));
}
__device__ __forceinline__ float sigf(float x) {
    return __fdividef(1.0f, 1.0f + __expf(-x));
}
__device__ __forceinline__ float tanhfast(float x) {
    return 1.0f - __fdividef(2.0f, __expf(2.0f * x) + 1.0f);
}

// ---------------- prep: permute cols (gate-interleave) + fp16 convert/split ----------
__global__ void prep_kernel(const float *__restrict__ rnn,
                            const float *__restrict__ h0,
                            const float *__restrict__ Ww,
                            const float *__restrict__ Uw)
{
    if (blockIdx.x == 0 && threadIdx.x < 256)
        g_arrm[threadIdx.x] = 0u;
    const long TU = 512L * 2048, TW = 256L * 2048, TX = 256L * 256, TH = 256L * 512;
    const long TOT = TU + TW + TX + TH;
    for (long i = (long)blockIdx.x * blockDim.x + threadIdx.x; i < TOT;
         i += (long)gridDim.x * blockDim.x) {
        if (i < TU) {
            long k = i >> 11;
            int n = (int)(i & 2047);
            int p = ((n & 511) << 2) | (n >> 9);   // h*4 + gate
            g_Uf[(long)p * 512 + k] = __float2half_rn(Uw[i]);
        } else if (i < TU + TW) {
            long j = i - TU;
            long k = j >> 11;
            int n = (int)(j & 2047);
            int p = ((n & 511) << 2) | (n >> 9);
            g_Wf[(long)p * 256 + k] = __float2half_rn(Ww[j]);
        } else if (i < TU + TW + TX) {
            long j = i - TU - TW;
            float v = rnn[j];
            __half hi = __float2half_rn(v);
            g_x0h[j] = hi;
            g_x0l[j] = __float2half_rn(v - __half2float(hi));
        } else {
            long j = i - TU - TW - TX;
            g_ah[0][j] = __float2half_rn(h0[j]);
        }
    }
}

// ---------------- A chunk fill: 32 rows x 256 k fp16 into chunk buffer c ----------
__device__ __forceinline__ void fill_chunk(const __half *__restrict__ gh, int ldk,
                                           int m0, int c, uint32_t smb, int tid)
{
#pragma unroll
    for (int i = 0; i < 8; ++i) {
        int u = tid + NTHR * i, m = u >> 5, kg = u & 31;
        size_t go = (size_t)(m0 + m) * ldk + c * 256 + kg * 8;
        uint32_t d = (uint32_t)((c & 1) * AB1 + m * 512 + ((kg * 16) ^ ((m & 7) << 4)));
        cpa16(smb + d, gh + go);
    }
}

// ---------------- compute one K256 chunk: warp m32n32, C[8][4] ----------------
__device__ __forceinline__ void compute_chunk(uint32_t ab, uint32_t smb, int kc,
                                              int lane, int wn, float C[8][4])
{
#pragma unroll
    for (int sub = 0; sub < 16; ++sub) {
        uint32_t ahr[2][4];
        {
            int mat = lane >> 3, rr = lane & 7;
            int kb = sub * 32 + ((mat >> 1) << 4);
#pragma unroll
            for (int ms = 0; ms < 2; ++ms) {
                int mloc = ms * 16 + ((mat & 1) << 3) + rr;
                uint32_t off = mloc * 512 + (kb ^ ((mloc & 7) << 4));
                ldsm4(ab + off, ahr[ms]);
            }
        }
        uint32_t bf[8];
        const int kg2 = (kc * 256 + sub * 16) * 2;
#pragma unroll
        for (int half = 0; half < 2; ++half) {
            int mat = lane >> 3, rr = lane & 7;
            int nloc = wn * 32 + half * 16 + ((mat >> 1) << 3) + rr;
            int kb = kg2 + ((mat & 1) << 4);
            uint32_t off = nloc * 1024 + (kb ^ ((nloc & 7) << 4));
            ldsm4(smb + SO_U + off, &bf[half * 4]);
        }
#pragma unroll
        for (int ms = 0; ms < 2; ++ms)
#pragma unroll
            for (int nb = 0; nb < 4; ++nb)
                mmaf16(C[ms * 4 + nb], ahr[ms], bf[nb * 2], bf[nb * 2 + 1]);
    }
}

// ---------------- pre GEMM: 2-pass split fp16 (x0), K=256 single chunk -------------
__device__ __forceinline__ void run_pre(
    const __half *__restrict__ gh, const __half *__restrict__ gl,
    int m0, uint32_t smb, int tid, int lane, int wn, float C[8][4])
{
#pragma unroll
    for (int i = 0; i < 8; ++i) {
        int u = tid + NTHR * i, m = u >> 5, kg = u & 31;
        size_t go = (size_t)(m0 + m) * II + kg * 8;
        uint32_t d = (uint32_t)(m * 512 + ((kg * 16) ^ ((m & 7) << 4)));
        cpa16(smb + d, gh + go);
        cpa16(smb + d + SO_AL, gl + go);
    }
    CP_COMMIT;
    asm volatile("cp.async.wait_group 0;" ::: "memory");
    __syncthreads();
#pragma unroll
    for (int sub = 0; sub < 16; ++sub) {
        uint32_t ahr[2][4], alr[2][4];
        {
            int mat = lane >> 3, rr = lane & 7;
            int kb = sub * 32 + ((mat >> 1) << 4);
#pragma unroll
            for (int ms = 0; ms < 2; ++ms) {
                int mloc = ms * 16 + ((mat & 1) << 3) + rr;
                uint32_t off = mloc * 512 + (kb ^ ((mloc & 7) << 4));
                ldsm4(smb + off, ahr[ms]);
                ldsm4(smb + SO_AL + off, alr[ms]);
            }
        }
        uint32_t bf[8];
        const int kg2 = (sub * 16) * 2;
#pragma unroll
        for (int half = 0; half < 2; ++half) {
            int mat = lane >> 3, rr = lane & 7;
            int nloc = wn * 32 + half * 16 + ((mat >> 1) << 3) + rr;
            int kb = kg2 + ((mat & 1) << 4);
            uint32_t off = nloc * 512 + (kb ^ ((nloc & 7) << 4));
            ldsm4(smb + SO_U + off, &bf[half * 4]);
        }
#pragma unroll
        for (int ms = 0; ms < 2; ++ms)
#pragma unroll
            for (int nb = 0; nb < 4; ++nb) {
                mmaf16(C[ms * 4 + nb], ahr[ms], bf[nb * 2], bf[nb * 2 + 1]);
                mmaf16(C[ms * 4 + nb], alr[ms], bf[nb * 2], bf[nb * 2 + 1]);
            }
    }
}

// ---------------- main persistent kernel ----------------
__global__ void __launch_bounds__(NTHR, 1) lstm_mma(
    const int *__restrict__ bsz, const float *__restrict__ h0in,
    const float *__restrict__ c0in, const float *__restrict__ taup,
    const float *__restrict__ Wb, float *__restrict__ out)
{
    extern __shared__ char sm[];
    const uint32_t smb = smem_u32(sm);
    const int tid = threadIdx.x, cta = blockIdx.x;
    const int lane = tid & 31, wn = tid >> 5;        // 4 warps, m32n32 each
    const int mtile = cta & 7, ntile = cta >> 3;     // 8 mtiles x 16 ntiles
    const int m0 = mtile * 32;
    const float tauv = __ldg(taup);
    unsigned *mybar = &g_arrm[mtile * 32];

    const int cc = lane & 3;
    const int hbash = ntile * 32 + wn * 8 + (cc >> 1);
    const int mg0 = m0 + (lane >> 2);                // rows mg0 + ms*16 + mh*8

    // ---- fill W slice (n128 x k256, pitch 512B) into U slot, compute pre ----
    {
        char *p = sm;
#pragma unroll
        for (int i = 0; i < 32; ++i) {
            int u = tid + NTHR * i, n = u >> 5, kg = u & 31;
            uint32_t d = n * 512 + ((kg * 16) ^ ((n & 7) << 4));
            *(uint4 *)(p + SO_U + d) =
                *(const uint4 *)(g_Wf + (size_t)(ntile * 128 + n) * 256 + kg * 8);
        }
    }
    __syncthreads();

    float C[8][4];
#pragma unroll
    for (int a = 0; a < 8; ++a)
#pragma unroll
        for (int r = 0; r < 4; ++r) C[a][r] = 0.0f;
    run_pre(g_x0h, g_x0l, m0, smb, tid, lane, wn, C);

    float pre[8][4];
#pragma unroll
    for (int ms = 0; ms < 2; ++ms)
#pragma unroll
        for (int nb = 0; nb < 4; ++nb)
#pragma unroll
            for (int r = 0; r < 4; ++r) {
                int gate = (cc * 2 + (r & 1)) & 3;
                int hg = ntile * 32 + wn * 8 + nb * 2 + (cc >> 1);
                pre[ms * 4 + nb][r] = C[ms * 4 + nb][r] + __ldg(Wb + gate * 512 + hg);
            }
    __syncthreads();

    // ---- fill U resident (n128 x k512, pitch 1024B, fp16, 128KB) ----
    {
        char *p = sm;
#pragma unroll
        for (int i = 0; i < 64; ++i) {
            int u = tid + NTHR * i, n = u >> 6, kg = u & 63;
            uint32_t d = n * 1024 + ((kg * 16) ^ ((n & 7) << 4));
            *(uint4 *)(p + SO_U + d) =
                *(const uint4 *)(g_Uf + (size_t)(ntile * 128 + n) * 512 + kg * 8);
        }
    }
    __syncthreads();

    // ---- per-thread cell states (8 cells: [p][ms][mh]); fp32 resident ----
    float cs[2][2][2], hs[2][2][2];
#pragma unroll
    for (int p = 0; p < 2; ++p) {
        int nb = (lane & 1) ? 2 + p : p;
        int hg = hbash + nb * 2;
#pragma unroll
        for (int ms = 0; ms < 2; ++ms)
#pragma unroll
            for (int mh = 0; mh < 2; ++mh) {
                int mg = mg0 + ms * 16 + mh * 8;
                cs[p][ms][mh] = __ldg(c0in + (size_t)mg * 512 + hg);
                hs[p][ms][mh] = __ldg(h0in + (size_t)mg * 512 + hg);
            }
    }

    // ---- time loop: per-mtile monotone-counter barrier (16 CTAs/group) ----
    for (int t = 0; t < TT; ++t) {
        const __half *gh = g_ah[t & 1];
#pragma unroll
        for (int a = 0; a < 8; ++a)
#pragma unroll
            for (int r = 0; r < 4; ++r) C[a][r] = 0.0f;

        __syncthreads();   // A-buffer reuse guard
        fill_chunk(gh, HH, m0, 0, smb, tid);
        CP_COMMIT;
        fill_chunk(gh, HH, m0, 1, smb, tid);
        CP_COMMIT;
        asm volatile("cp.async.wait_group 1;" ::: "memory");
        __syncthreads();
        compute_chunk(smb, smb, 0, lane, wn, C);
        asm volatile("cp.async.wait_group 0;" ::: "memory");
        __syncthreads();
        compute_chunk(smb + AB1, smb, 1, lane, wn, C);

        const int bs = __ldg(bsz + t);

        // gate sums = C + pre; exchange complementary gate pairs with lane^1
        float own[2][2][4], R[2][2][4];
#pragma unroll
        for (int p = 0; p < 2; ++p)
#pragma unroll
            for (int ms = 0; ms < 2; ++ms)
#pragma unroll
                for (int r = 0; r < 4; ++r) {
                    float lo2 = C[ms * 4 + p][r] + pre[ms * 4 + p][r];
                    float hi2 = C[ms * 4 + 2 + p][r] + pre[ms * 4 + 2 + p][r];
                    own[p][ms][r] = (lane & 1) ? hi2 : lo2;
                    float send = (lane & 1) ? lo2 : hi2;
                    R[p][ms][r] = __shfl_xor_sync(0xffffffffu, send, 1);
                }

        float o4[2][2][2];
#pragma unroll
        for (int p = 0; p < 2; ++p)
#pragma unroll
            for (int ms = 0; ms < 2; ++ms)
#pragma unroll
                for (int mh = 0; mh < 2; ++mh) {
                    float vi, vf, vg, vo;
                    if (lane & 1) {
                        vg = own[p][ms][mh * 2]; vo = own[p][ms][mh * 2 + 1];
                        vi = R[p][ms][mh * 2];   vf = R[p][ms][mh * 2 + 1];
                    } else {
                        vi = own[p][ms][mh * 2]; vf = own[p][ms][mh * 2 + 1];
                        vg = R[p][ms][mh * 2];   vo = R[p][ms][mh * 2 + 1];
                    }
                    int mg = mg0 + ms * 16 + mh * 8;
                    float cn = sigf(vf) * cs[p][ms][mh] + sigf(vi) * tanhfast(vg);
                    float hn = sigf(vo) * tanhfast(cn);
                    bool act = (mg < bs);
                    o4[p][ms][mh] = act ? hn : 0.0f;
                    if (act) { cs[p][ms][mh] = cn; hs[p][ms][mh] = hn; }
                }

        if (t < TT - 1) {
            // drift on h dims 0,1 (ntile 0, wn 0, nb 0 → even lanes, cc 0 and 2)
            if (ntile == 0 && wn == 0) {
#pragma unroll
                for (int ms = 0; ms < 2; ++ms)
#pragma unroll
                    for (int mh = 0; mh < 2; ++mh) {
                        float mine = hs[0][ms][mh];
                        float oth = __shfl_xor_sync(0xffffffffu, mine, 2);
                        if (!(lane & 1)) {
                            if (cc == 0)
                                hs[0][ms][mh] =
                                    mine + tauv * (1.5f * mine + oth * (1.0f / 1.5f));
                            else if (cc == 2)
                                hs[0][ms][mh] = mine - tauv * (1.5f * oth);
                        }
                    }
            }
            __half *dh = g_ah[(t + 1) & 1];
#pragma unroll
            for (int p = 0; p < 2; ++p) {
                int nb = (lane & 1) ? 2 + p : p;
                int hg = hbash + nb * 2;
#pragma unroll
                for (int ms = 0; ms < 2; ++ms)
#pragma unroll
                    for (int mh = 0; mh < 2; ++mh) {
                        int mg = mg0 + ms * 16 + mh * 8;
                        dh[(size_t)mg * 512 + hg] = __float2half_rn(hs[p][ms][mh]);
                    }
            }
            // release h writes, arrive; overlap out-stores with barrier wait
            __threadfence();
            __syncthreads();
            if (tid == 0) atomicAdd(mybar, 1u);
#pragma unroll
            for (int p = 0; p < 2; ++p) {
                int nb = (lane & 1) ? 2 + p : p;
                int hg = hbash + nb * 2;
#pragma unroll
                for (int ms = 0; ms < 2; ++ms)
#pragma unroll
                    for (int mh = 0; mh < 2; ++mh) {
                        int mg = mg0 + ms * 16 + mh * 8;
                        out[(size_t)t * BH + (size_t)mg * 512 + hg] = o4[p][ms][mh];
                    }
            }
            if (tid == 0) {
                const unsigned tgt = (unsigned)(t + 1) * 16u;
                while (ldacq(mybar) < tgt) {}
            }
            __syncthreads();
        } else {
#pragma unroll
            for (int p = 0; p < 2; ++p) {
                int nb = (lane & 1) ? 2 + p : p;
                int hg = hbash + nb * 2;
#pragma unroll
                for (int ms = 0; ms < 2; ++ms)
#pragma unroll
                    for (int mh = 0; mh < 2; ++mh) {
                        int mg = mg0 + ms * 16 + mh * 8;
                        out[(size_t)t * BH + (size_t)mg * 512 + hg] = o4[p][ms][mh];
                    }
            }
        }
    }

    // ---- final h, c (from fp32 registers) ----
    const size_t ofs = (size_t)TT * BH;
#pragma unroll
    for (int p = 0; p < 2; ++p) {
        int nb = (lane & 1) ? 2 + p : p;
        int hg = hbash + nb * 2;
#pragma unroll
        for (int ms = 0; ms < 2; ++ms)
#pragma unroll
            for (int mh = 0; mh < 2; ++mh) {
                int mg = mg0 + ms * 16 + mh * 8;
                out[ofs + (size_t)mg * 512 + hg] = hs[p][ms][mh];
                out[ofs + BH + (size_t)mg * 512 + hg] = cs[p][ms][mh];
            }
    }
}

extern "C" void kernel_launch(void *const *d_in, const int *in_sizes, int n_in,
                              void *d_out, int out_size)
{
    const float *rnn = (const float *)d_in[0];
    const int *bsz = (const int *)d_in[1];
    const float *h0 = (const float *)d_in[2];
    const float *c0 = (const float *)d_in[3];
    const float *tau = (const float *)d_in[4];
    const float *Ww = (const float *)d_in[5];
    const float *Wb = (const float *)d_in[6];
    const float *Uw = (const float *)d_in[7];
    float *out = (float *)d_out;

    cudaFuncSetAttribute(lstm_mma, cudaFuncAttributeMaxDynamicSharedMemorySize,
                         SMEM_TOT);
    prep_kernel<<<512, 256>>>(rnn, h0, Ww, Uw);
    lstm_mma<<<NCTA, NTHR, SMEM_TOT>>>(bsz, h0, c0, tau, Wb, out);
}

// round 15
// speedup vs baseline: 1.4034x; 1.0549x over previous
#include <cuda_runtime.h>
#include <cuda_fp16.h>
#include <stdint.h>

#define BB 256
#define TT 512
#define HH 512
#define II 256
#define BH 131072
#define NCTA 128
#define NTHR 128

// CTA tile: m32 x n128, 4 warps of m32n32. 8 mtiles x 16 ntiles.
// SMEM: A chunk dbl-buf 2 x 16K = 32K, A lo (pre GEMM only) at 32K..48K,
//       U (fp16, n128 x k512, pitch 1024B) at 64K..192K
#define AB1   16384
#define SO_AL 32768
#define SO_U  65536
#define SMEM_TOT 196608

// ---------------- device globals ----------------
__device__ __align__(16) __half g_Uf[2048 * 512];   // permuted U, fp16
__device__ __align__(16) __half g_Wf[2048 * 256];   // permuted W, fp16
__device__ __align__(16) __half g_x0h[256 * 256];
__device__ __align__(16) __half g_x0l[256 * 256];
__device__ __align__(16) __half g_ah[2][BH];        // h stream (fp16, 1-pass)
__device__ unsigned int g_arrm[8 * 32];             // per-mtile counters, 128B apart

// ---------------- helpers ----------------
__device__ __forceinline__ uint32_t smem_u32(const void *p) {
    uint32_t a;
    asm("{ .reg .u64 t; cvta.to.shared.u64 t, %1; cvt.u32.u64 %0, t; }"
        : "=r"(a) : "l"(p));
    return a;
}
__device__ __forceinline__ void cpa16(uint32_t dst, const void *src) {
    asm volatile("cp.async.cg.shared.global [%0], [%1], 16;"
                 :: "r"(dst), "l"(__cvta_generic_to_global(src)) : "memory");
}
#define CP_COMMIT asm volatile("cp.async.commit_group;" ::: "memory")

__device__ __forceinline__ unsigned ldacq(const unsigned *p) {
    unsigned v;
    asm volatile("ld.acquire.gpu.global.u32 %0, [%1];"
                 : "=r"(v) : "l"(__cvta_generic_to_global((void *)p)) : "memory");
    return v;
}
__device__ __forceinline__ void ldsm4(uint32_t addr, uint32_t r[4]) {
    asm volatile("ldmatrix.sync.aligned.m8n8.x4.shared.b16 {%0,%1,%2,%3}, [%4];"
                 : "=r"(r[0]), "=r"(r[1]), "=r"(r[2]), "=r"(r[3]) : "r"(addr));
}
__device__ __forceinline__ void mmaf16(float c[4], const uint32_t a[4],
                                       uint32_t b0, uint32_t b1) {
    asm volatile(
        "mma.sync.aligned.m16n8k16.row.col.f32.f16.f16.f32 "
        "{%0,%1,%2,%3}, {%4,%5,%6,%7}, {%8,%9}, {%0,%1,%2,%3};"
        : "+f"(c[0]), "+f"(c[1]), "+f"(c[2]), "+f"(c[3])
        : "r"(a[0]), "r"(a[1]), "r"(a[2]), "r"(a[3]), "r"(b0), "r"(b1));
}
__device__ __forceinline__ float sigf(float x) {
    return __fdividef(1.0f, 1.0f + __expf(-x));
}
__device__ __forceinline__ float tanhfast(float x) {
    return 1.0f - __fdividef(2.0f, __expf(2.0f * x) + 1.0f);
}

// ---------------- prep: permute cols (gate-interleave) + fp16 convert/split ----------
__global__ void prep_kernel(const float *__restrict__ rnn,
                            const float *__restrict__ h0,
                            const float *__restrict__ Ww,
                            const float *__restrict__ Uw)
{
    if (blockIdx.x == 0 && threadIdx.x < 256)
        g_arrm[threadIdx.x] = 0u;
    const long TU = 512L * 2048, TW = 256L * 2048, TX = 256L * 256, TH = 256L * 512;
    const long TOT = TU + TW + TX + TH;
    for (long i = (long)blockIdx.x * blockDim.x + threadIdx.x; i < TOT;
         i += (long)gridDim.x * blockDim.x) {
        if (i < TU) {
            long k = i >> 11;
            int n = (int)(i & 2047);
            int p = ((n & 511) << 2) | (n >> 9);   // h*4 + gate
            g_Uf[(long)p * 512 + k] = __float2half_rn(Uw[i]);
        } else if (i < TU + TW) {
            long j = i - TU;
            long k = j >> 11;
            int n = (int)(j & 2047);
            int p = ((n & 511) << 2) | (n >> 9);
            g_Wf[(long)p * 256 + k] = __float2half_rn(Ww[j]);
        } else if (i < TU + TW + TX) {
            long j = i - TU - TW;
            float v = rnn[j];
            __half hi = __float2half_rn(v);
            g_x0h[j] = hi;
            g_x0l[j] = __float2half_rn(v - __half2float(hi));
        } else {
            long j = i - TU - TW - TX;
            g_ah[0][j] = __float2half_rn(h0[j]);
        }
    }
}

// ---------------- A chunk fill: 32 rows x 256 k fp16 into chunk buffer c ----------
__device__ __forceinline__ void fill_chunk(const __half *__restrict__ gh, int ldk,
                                           int m0, int c, uint32_t smb, int tid)
{
#pragma unroll
    for (int i = 0; i < 8; ++i) {
        int u = tid + NTHR * i, m = u >> 5, kg = u & 31;
        size_t go = (size_t)(m0 + m) * ldk + c * 256 + kg * 8;
        uint32_t d = (uint32_t)((c & 1) * AB1 + m * 512 + ((kg * 16) ^ ((m & 7) << 4)));
        cpa16(smb + d, gh + go);
    }
}

// ---------------- compute one K256 chunk: warp m32n32, C[8][4] ----------------
__device__ __forceinline__ void compute_chunk(uint32_t ab, uint32_t smb, int kc,
                                              int lane, int wn, float C[8][4])
{
#pragma unroll
    for (int sub = 0; sub < 16; ++sub) {
        uint32_t ahr[2][4];
        {
            int mat = lane >> 3, rr = lane & 7;
            int kb = sub * 32 + ((mat >> 1) << 4);
#pragma unroll
            for (int ms = 0; ms < 2; ++ms) {
                int mloc = ms * 16 + ((mat & 1) << 3) + rr;
                uint32_t off = mloc * 512 + (kb ^ ((mloc & 7) << 4));
                ldsm4(ab + off, ahr[ms]);
            }
        }
        uint32_t bf[8];
        const int kg2 = (kc * 256 + sub * 16) * 2;
#pragma unroll
        for (int half = 0; half < 2; ++half) {
            int mat = lane >> 3, rr = lane & 7;
            int nloc = wn * 32 + half * 16 + ((mat >> 1) << 3) + rr;
            int kb = kg2 + ((mat & 1) << 4);
            uint32_t off = nloc * 1024 + (kb ^ ((nloc & 7) << 4));
            ldsm4(smb + SO_U + off, &bf[half * 4]);
        }
#pragma unroll
        for (int ms = 0; ms < 2; ++ms)
#pragma unroll
            for (int nb = 0; nb < 4; ++nb)
                mmaf16(C[ms * 4 + nb], ahr[ms], bf[nb * 2], bf[nb * 2 + 1]);
    }
}

// ---------------- pre GEMM: 2-pass split fp16 (x0), K=256 single chunk -------------
__device__ __forceinline__ void run_pre(
    const __half *__restrict__ gh, const __half *__restrict__ gl,
    int m0, uint32_t smb, int tid, int lane, int wn, float C[8][4])
{
#pragma unroll
    for (int i = 0; i < 8; ++i) {
        int u = tid + NTHR * i, m = u >> 5, kg = u & 31;
        size_t go = (size_t)(m0 + m) * II + kg * 8;
        uint32_t d = (uint32_t)(m * 512 + ((kg * 16) ^ ((m & 7) << 4)));
        cpa16(smb + d, gh + go);
        cpa16(smb + d + SO_AL, gl + go);
    }
    CP_COMMIT;
    asm volatile("cp.async.wait_group 0;" ::: "memory");
    __syncthreads();
#pragma unroll
    for (int sub = 0; sub < 16; ++sub) {
        uint32_t ahr[2][4], alr[2][4];
        {
            int mat = lane >> 3, rr = lane & 7;
            int kb = sub * 32 + ((mat >> 1) << 4);
#pragma unroll
            for (int ms = 0; ms < 2; ++ms) {
                int mloc = ms * 16 + ((mat & 1) << 3) + rr;
                uint32_t off = mloc * 512 + (kb ^ ((mloc & 7) << 4));
                ldsm4(smb + off, ahr[ms]);
                ldsm4(smb + SO_AL + off, alr[ms]);
            }
        }
        uint32_t bf[8];
        const int kg2 = (sub * 16) * 2;
#pragma unroll
        for (int half = 0; half < 2; ++half) {
            int mat = lane >> 3, rr = lane & 7;
            int nloc = wn * 32 + half * 16 + ((mat >> 1) << 3) + rr;
            int kb = kg2 + ((mat & 1) << 4);
            uint32_t off = nloc * 512 + (kb ^ ((nloc & 7) << 4));
            ldsm4(smb + SO_U + off, &bf[half * 4]);
        }
#pragma unroll
        for (int ms = 0; ms < 2; ++ms)
#pragma unroll
            for (int nb = 0; nb < 4; ++nb) {
                mmaf16(C[ms * 4 + nb], ahr[ms], bf[nb * 2], bf[nb * 2 + 1]);
                mmaf16(C[ms * 4 + nb], alr[ms], bf[nb * 2], bf[nb * 2 + 1]);
            }
    }
}

// ---------------- main persistent kernel ----------------
__global__ void __launch_bounds__(NTHR, 1) lstm_mma(
    const int *__restrict__ bsz, const float *__restrict__ h0in,
    const float *__restrict__ c0in, const float *__restrict__ taup,
    const float *__restrict__ Wb, float *__restrict__ out)
{
    extern __shared__ char sm[];
    const uint32_t smb = smem_u32(sm);
    const int tid = threadIdx.x, cta = blockIdx.x;
    const int lane = tid & 31, wn = tid >> 5;        // 4 warps, m32n32 each
    const int mtile = cta & 7, ntile = cta >> 3;     // 8 mtiles x 16 ntiles
    const int m0 = mtile * 32;
    const float tauv = __ldg(taup);
    unsigned *mybar = &g_arrm[mtile * 32];

    const int cc = lane & 3;
    const int hbash = ntile * 32 + wn * 8 + (cc >> 1);
    const int mg0 = m0 + (lane >> 2);                // rows mg0 + ms*16 + mh*8

    // ---- fill W slice (n128 x k256, pitch 512B) into U slot, compute pre ----
    {
        char *p = sm;
#pragma unroll
        for (int i = 0; i < 32; ++i) {
            int u = tid + NTHR * i, n = u >> 5, kg = u & 31;
            uint32_t d = n * 512 + ((kg * 16) ^ ((n & 7) << 4));
            *(uint4 *)(p + SO_U + d) =
                *(const uint4 *)(g_Wf + (size_t)(ntile * 128 + n) * 256 + kg * 8);
        }
    }
    __syncthreads();

    float C[8][4];
#pragma unroll
    for (int a = 0; a < 8; ++a)
#pragma unroll
        for (int r = 0; r < 4; ++r) C[a][r] = 0.0f;
    run_pre(g_x0h, g_x0l, m0, smb, tid, lane, wn, C);

    float pre[8][4];
#pragma unroll
    for (int ms = 0; ms < 2; ++ms)
#pragma unroll
        for (int nb = 0; nb < 4; ++nb)
#pragma unroll
            for (int r = 0; r < 4; ++r) {
                int gate = (cc * 2 + (r & 1)) & 3;
                int hg = ntile * 32 + wn * 8 + nb * 2 + (cc >> 1);
                pre[ms * 4 + nb][r] = C[ms * 4 + nb][r] + __ldg(Wb + gate * 512 + hg);
            }
    __syncthreads();

    // ---- fill U resident (n128 x k512, pitch 1024B, fp16, 128KB) ----
    {
        char *p = sm;
#pragma unroll
        for (int i = 0; i < 64; ++i) {
            int u = tid + NTHR * i, n = u >> 6, kg = u & 63;
            uint32_t d = n * 1024 + ((kg * 16) ^ ((n & 7) << 4));
            *(uint4 *)(p + SO_U + d) =
                *(const uint4 *)(g_Uf + (size_t)(ntile * 128 + n) * 512 + kg * 8);
        }
    }
    __syncthreads();

    // ---- per-thread cell states (8 cells: [p][ms][mh]); fp32 resident ----
    float cs[2][2][2], hs[2][2][2];
#pragma unroll
    for (int p = 0; p < 2; ++p) {
        int nb = (lane & 1) ? 2 + p : p;
        int hg = hbash + nb * 2;
#pragma unroll
        for (int ms = 0; ms < 2; ++ms)
#pragma unroll
            for (int mh = 0; mh < 2; ++mh) {
                int mg = mg0 + ms * 16 + mh * 8;
                cs[p][ms][mh] = __ldg(c0in + (size_t)mg * 512 + hg);
                hs[p][ms][mh] = __ldg(h0in + (size_t)mg * 512 + hg);
            }
    }

    // ---- time loop: per-mtile monotone-counter barrier (16 CTAs/group) ----
    for (int t = 0; t < TT; ++t) {
        const __half *gh = g_ah[t & 1];
#pragma unroll
        for (int a = 0; a < 8; ++a)
#pragma unroll
            for (int r = 0; r < 4; ++r) C[a][r] = 0.0f;

        __syncthreads();   // A-buffer reuse guard
        fill_chunk(gh, HH, m0, 0, smb, tid);
        CP_COMMIT;
        fill_chunk(gh, HH, m0, 1, smb, tid);
        CP_COMMIT;
        asm volatile("cp.async.wait_group 1;" ::: "memory");
        __syncthreads();
        compute_chunk(smb, smb, 0, lane, wn, C);
        asm volatile("cp.async.wait_group 0;" ::: "memory");
        __syncthreads();
        compute_chunk(smb + AB1, smb, 1, lane, wn, C);

        const int bs = __ldg(bsz + t);

        // gate sums = C + pre; exchange complementary gate pairs with lane^1
        float own[2][2][4], R[2][2][4];
#pragma unroll
        for (int p = 0; p < 2; ++p)
#pragma unroll
            for (int ms = 0; ms < 2; ++ms)
#pragma unroll
                for (int r = 0; r < 4; ++r) {
                    float lo2 = C[ms * 4 + p][r] + pre[ms * 4 + p][r];
                    float hi2 = C[ms * 4 + 2 + p][r] + pre[ms * 4 + 2 + p][r];
                    own[p][ms][r] = (lane & 1) ? hi2 : lo2;
                    float send = (lane & 1) ? lo2 : hi2;
                    R[p][ms][r] = __shfl_xor_sync(0xffffffffu, send, 1);
                }

        float o4[2][2][2];
#pragma unroll
        for (int p = 0; p < 2; ++p)
#pragma unroll
            for (int ms = 0; ms < 2; ++ms)
#pragma unroll
                for (int mh = 0; mh < 2; ++mh) {
                    float vi, vf, vg, vo;
                    if (lane & 1) {
                        vg = own[p][ms][mh * 2]; vo = own[p][ms][mh * 2 + 1];
                        vi = R[p][ms][mh * 2];   vf = R[p][ms][mh * 2 + 1];
                    } else {
                        vi = own[p][ms][mh * 2]; vf = own[p][ms][mh * 2 + 1];
                        vg = R[p][ms][mh * 2];   vo = R[p][ms][mh * 2 + 1];
                    }
                    int mg = mg0 + ms * 16 + mh * 8;
                    float cn = sigf(vf) * cs[p][ms][mh] + sigf(vi) * tanhfast(vg);
                    float hn = sigf(vo) * tanhfast(cn);
                    bool act = (mg < bs);
                    o4[p][ms][mh] = act ? hn : 0.0f;
                    if (act) { cs[p][ms][mh] = cn; hs[p][ms][mh] = hn; }
                }

        if (t < TT - 1) {
            // drift on h dims 0,1 (ntile 0, wn 0, nb 0 → even lanes, cc 0 and 2)
            if (ntile == 0 && wn == 0) {
#pragma unroll
                for (int ms = 0; ms < 2; ++ms)
#pragma unroll
                    for (int mh = 0; mh < 2; ++mh) {
                        float mine = hs[0][ms][mh];
                        float oth = __shfl_xor_sync(0xffffffffu, mine, 2);
                        if (!(lane & 1)) {
                            if (cc == 0)
                                hs[0][ms][mh] =
                                    mine + tauv * (1.5f * mine + oth * (1.0f / 1.5f));
                            else if (cc == 2)
                                hs[0][ms][mh] = mine - tauv * (1.5f * oth);
                        }
                    }
            }
            __half *dh = g_ah[(t + 1) & 1];
#pragma unroll
            for (int p = 0; p < 2; ++p) {
                int nb = (lane & 1) ? 2 + p : p;
                int hg = hbash + nb * 2;
#pragma unroll
                for (int ms = 0; ms < 2; ++ms)
#pragma unroll
                    for (int mh = 0; mh < 2; ++mh) {
                        int mg = mg0 + ms * 16 + mh * 8;
                        dh[(size_t)mg * 512 + hg] = __float2half_rn(hs[p][ms][mh]);
                    }
            }
            // release h writes, arrive; overlap out-stores with barrier wait
            __threadfence();
            __syncthreads();
            if (tid == 0) atomicAdd(mybar, 1u);
#pragma unroll
            for (int p = 0; p < 2; ++p) {
                int nb = (lane & 1) ? 2 + p : p;
                int hg = hbash + nb * 2;
#pragma unroll
                for (int ms = 0; ms < 2; ++ms)
#pragma unroll
                    for (int mh = 0; mh < 2; ++mh) {
                        int mg = mg0 + ms * 16 + mh * 8;
                        out[(size_t)t * BH + (size_t)mg * 512 + hg] = o4[p][ms][mh];
                    }
            }
            if (tid == 0) {
                const unsigned tgt = (unsigned)(t + 1) * 16u;
                while (ldacq(mybar) < tgt) {}
            }
            __syncthreads();
        } else {
#pragma unroll
            for (int p = 0; p < 2; ++p) {
                int nb = (lane & 1) ? 2 + p : p;
                int hg = hbash + nb * 2;
#pragma unroll
                for (int ms = 0; ms < 2; ++ms)
#pragma unroll
                    for (int mh = 0; mh < 2; ++mh) {
                        int mg = mg0 + ms * 16 + mh * 8;
                        out[(size_t)t * BH + (size_t)mg * 512 + hg] = o4[p][ms][mh];
                    }
            }
        }
    }

    // ---- final h, c (from fp32 registers) ----
    const size_t ofs = (size_t)TT * BH;
#pragma unroll
    for (int p = 0; p < 2; ++p) {
        int nb = (lane & 1) ? 2 + p : p;
        int hg = hbash + nb * 2;
#pragma unroll
        for (int ms = 0; ms < 2; ++ms)
#pragma unroll
            for (int mh = 0; mh < 2; ++mh) {
                int mg = mg0 + ms * 16 + mh * 8;
                out[ofs + (size_t)mg * 512 + hg] = hs[p][ms][mh];
                out[ofs + BH + (size_t)mg * 512 + hg] = cs[p][ms][mh];
            }
    }
}

extern "C" void kernel_launch(void *const *d_in, const int *in_sizes, int n_in,
                              void *d_out, int out_size)
{
    const float *rnn = (const float *)d_in[0];
    const int *bsz = (const int *)d_in[1];
    const float *h0 = (const float *)d_in[2];
    const float *c0 = (const float *)d_in[3];
    const float *tau = (const float *)d_in[4];
    const float *Ww = (const float *)d_in[5];
    const float *Wb = (const float *)d_in[6];
    const float *Uw = (const float *)d_in[7];
    float *out = (float *)d_out;

    cudaFuncSetAttribute(lstm_mma, cudaFuncAttributeMaxDynamicSharedMemorySize,
                         SMEM_TOT);
    prep_kernel<<<512, 256>>>(rnn, h0, Ww, Uw);
    lstm_mma<<<NCTA, NTHR, SMEM_TOT>>>(bsz, h0, c0, tau, Wb, out);
}

// round 16
// speedup vs baseline: 1.4039x; 1.0004x over previous
#include <cuda_runtime.h>
#include <cuda_fp16.h>
#include <stdint.h>

#define BB 256
#define TT 512
#define HH 512
#define II 256
#define BH 131072
#define NCTA 128
#define NTHR 128

// CTA tile: m32 x n128, 4 warps of m32n32. 8 mtiles x 16 ntiles.
// SMEM: A chunk dbl-buf 2 x 16K = 32K, A lo (pre GEMM only) at 32K..48K,
//       U (fp16, n128 x k512, pitch 1024B) at 64K..192K
#define AB1   16384
#define SO_AL 32768
#define SO_U  65536
#define SMEM_TOT 196608

// ---------------- device globals ----------------
__device__ __align__(16) __half g_Uf[2048 * 512];   // permuted U, fp16
__device__ __align__(16) __half g_Wf[2048 * 256];   // permuted W, fp16
__device__ __align__(16) __half g_x0h[256 * 256];
__device__ __align__(16) __half g_x0l[256 * 256];
__device__ __align__(16) __half g_ah[2][BH];        // h stream (fp16, 1-pass)
__device__ unsigned int g_arrm[8 * 32];             // per-mtile counters, 128B apart

// ---------------- helpers ----------------
__device__ __forceinline__ uint32_t smem_u32(const void *p) {
    uint32_t a;
    asm("{ .reg .u64 t; cvta.to.shared.u64 t, %1; cvt.u32.u64 %0, t; }"
        : "=r"(a) : "l"(p));
    return a;
}
__device__ __forceinline__ void cpa16(uint32_t dst, const void *src) {
    asm volatile("cp.async.cg.shared.global [%0], [%1], 16;"
                 :: "r"(dst), "l"(__cvta_generic_to_global(src)) : "memory");
}
#define CP_COMMIT asm volatile("cp.async.commit_group;" ::: "memory")

__device__ __forceinline__ unsigned ldacq(const unsigned *p) {
    unsigned v;
    asm volatile("ld.acquire.gpu.global.u32 %0, [%1];"
                 : "=r"(v) : "l"(__cvta_generic_to_global((void *)p)) : "memory");
    return v;
}
__device__ __forceinline__ void ldsm4(uint32_t addr, uint32_t r[4]) {
    asm volatile("ldmatrix.sync.aligned.m8n8.x4.shared.b16 {%0,%1,%2,%3}, [%4];"
                 : "=r"(r[0]), "=r"(r[1]), "=r"(r[2]), "=r"(r[3]) : "r"(addr));
}
__device__ __forceinline__ void mmaf16(float c[4], const uint32_t a[4],
                                       uint32_t b0, uint32_t b1) {
    asm volatile(
        "mma.sync.aligned.m16n8k16.row.col.f32.f16.f16.f32 "
        "{%0,%1,%2,%3}, {%4,%5,%6,%7}, {%8,%9}, {%0,%1,%2,%3};"
        : "+f"(c[0]), "+f"(c[1]), "+f"(c[2]), "+f"(c[3])
        : "r"(a[0]), "r"(a[1]), "r"(a[2]), "r"(a[3]), "r"(b0), "r"(b1));
}
__device__ __forceinline__ float sigf(float x) {
    return __fdividef(1.0f, 1.0f + __expf(-x));
}
__device__ __forceinline__ float tanhfast(float x) {
    return 1.0f - __fdividef(2.0f, __expf(2.0f * x) + 1.0f);
}

// ---------------- prep: permute cols (gate-interleave) + fp16 convert/split ----------
__global__ void prep_kernel(const float *__restrict__ rnn,
                            const float *__restrict__ h0,
                            const float *__restrict__ Ww,
                            const float *__restrict__ Uw)
{
    if (blockIdx.x == 0 && threadIdx.x < 256)
        g_arrm[threadIdx.x] = 0u;
    const long TU = 512L * 2048, TW = 256L * 2048, TX = 256L * 256, TH = 256L * 512;
    const long TOT = TU + TW + TX + TH;
    for (long i = (long)blockIdx.x * blockDim.x + threadIdx.x; i < TOT;
         i += (long)gridDim.x * blockDim.x) {
        if (i < TU) {
            long k = i >> 11;
            int n = (int)(i & 2047);
            int p = ((n & 511) << 2) | (n >> 9);   // h*4 + gate
            g_Uf[(long)p * 512 + k] = __float2half_rn(Uw[i]);
        } else if (i < TU + TW) {
            long j = i - TU;
            long k = j >> 11;
            int n = (int)(j & 2047);
            int p = ((n & 511) << 2) | (n >> 9);
            g_Wf[(long)p * 256 + k] = __float2half_rn(Ww[j]);
        } else if (i < TU + TW + TX) {
            long j = i - TU - TW;
            float v = rnn[j];
            __half hi = __float2half_rn(v);
            g_x0h[j] = hi;
            g_x0l[j] = __float2half_rn(v - __half2float(hi));
        } else {
            long j = i - TU - TW - TX;
            g_ah[0][j] = __float2half_rn(h0[j]);
        }
    }
}

// ---------------- A chunk fill: 32 rows x 256 k fp16 into chunk buffer c ----------
__device__ __forceinline__ void fill_chunk(const __half *__restrict__ gh, int ldk,
                                           int m0, int c, uint32_t smb, int tid)
{
#pragma unroll
    for (int i = 0; i < 8; ++i) {
        int u = tid + NTHR * i, m = u >> 5, kg = u & 31;
        size_t go = (size_t)(m0 + m) * ldk + c * 256 + kg * 8;
        uint32_t d = (uint32_t)((c & 1) * AB1 + m * 512 + ((kg * 16) ^ ((m & 7) << 4)));
        cpa16(smb + d, gh + go);
    }
}

// ---------------- compute one K256 chunk: warp m32n32, C[8][4] ----------------
__device__ __forceinline__ void compute_chunk(uint32_t ab, uint32_t smb, int kc,
                                              int lane, int wn, float C[8][4])
{
#pragma unroll
    for (int sub = 0; sub < 16; ++sub) {
        uint32_t ahr[2][4];
        {
            int mat = lane >> 3, rr = lane & 7;
            int kb = sub * 32 + ((mat >> 1) << 4);
#pragma unroll
            for (int ms = 0; ms < 2; ++ms) {
                int mloc = ms * 16 + ((mat & 1) << 3) + rr;
                uint32_t off = mloc * 512 + (kb ^ ((mloc & 7) << 4));
                ldsm4(ab + off, ahr[ms]);
            }
        }
        uint32_t bf[8];
        const int kg2 = (kc * 256 + sub * 16) * 2;
#pragma unroll
        for (int half = 0; half < 2; ++half) {
            int mat = lane >> 3, rr = lane & 7;
            int nloc = wn * 32 + half * 16 + ((mat >> 1) << 3) + rr;
            int kb = kg2 + ((mat & 1) << 4);
            uint32_t off = nloc * 1024 + (kb ^ ((nloc & 7) << 4));
            ldsm4(smb + SO_U + off, &bf[half * 4]);
        }
#pragma unroll
        for (int ms = 0; ms < 2; ++ms)
#pragma unroll
            for (int nb = 0; nb < 4; ++nb)
                mmaf16(C[ms * 4 + nb], ahr[ms], bf[nb * 2], bf[nb * 2 + 1]);
    }
}

// ---------------- pre GEMM: 2-pass split fp16 (x0), K=256 single chunk -------------
__device__ __forceinline__ void run_pre(
    const __half *__restrict__ gh, const __half *__restrict__ gl,
    int m0, uint32_t smb, int tid, int lane, int wn, float C[8][4])
{
#pragma unroll
    for (int i = 0; i < 8; ++i) {
        int u = tid + NTHR * i, m = u >> 5, kg = u & 31;
        size_t go = (size_t)(m0 + m) * II + kg * 8;
        uint32_t d = (uint32_t)(m * 512 + ((kg * 16) ^ ((m & 7) << 4)));
        cpa16(smb + d, gh + go);
        cpa16(smb + d + SO_AL, gl + go);
    }
    CP_COMMIT;
    asm volatile("cp.async.wait_group 0;" ::: "memory");
    __syncthreads();
#pragma unroll
    for (int sub = 0; sub < 16; ++sub) {
        uint32_t ahr[2][4], alr[2][4];
        {
            int mat = lane >> 3, rr = lane & 7;
            int kb = sub * 32 + ((mat >> 1) << 4);
#pragma unroll
            for (int ms = 0; ms < 2; ++ms) {
                int mloc = ms * 16 + ((mat & 1) << 3) + rr;
                uint32_t off = mloc * 512 + (kb ^ ((mloc & 7) << 4));
                ldsm4(smb + off, ahr[ms]);
                ldsm4(smb + SO_AL + off, alr[ms]);
            }
        }
        uint32_t bf[8];
        const int kg2 = (sub * 16) * 2;
#pragma unroll
        for (int half = 0; half < 2; ++half) {
            int mat = lane >> 3, rr = lane & 7;
            int nloc = wn * 32 + half * 16 + ((mat >> 1) << 3) + rr;
            int kb = kg2 + ((mat & 1) << 4);
            uint32_t off = nloc * 512 + (kb ^ ((nloc & 7) << 4));
            ldsm4(smb + SO_U + off, &bf[half * 4]);
        }
#pragma unroll
        for (int ms = 0; ms < 2; ++ms)
#pragma unroll
            for (int nb = 0; nb < 4; ++nb) {
                mmaf16(C[ms * 4 + nb], ahr[ms], bf[nb * 2], bf[nb * 2 + 1]);
                mmaf16(C[ms * 4 + nb], alr[ms], bf[nb * 2], bf[nb * 2 + 1]);
            }
    }
}

// ---------------- main persistent kernel ----------------
__global__ void __launch_bounds__(NTHR, 1) lstm_mma(
    const int *__restrict__ bsz, const float *__restrict__ h0in,
    const float *__restrict__ c0in, const float *__restrict__ taup,
    const float *__restrict__ Wb, float *__restrict__ out)
{
    extern __shared__ char sm[];
    const uint32_t smb = smem_u32(sm);
    const int tid = threadIdx.x, cta = blockIdx.x;
    const int lane = tid & 31, wn = tid >> 5;        // 4 warps, m32n32 each
    const int mtile = cta & 7, ntile = cta >> 3;     // 8 mtiles x 16 ntiles
    const int m0 = mtile * 32;
    const float tauv = __ldg(taup);
    unsigned *mybar = &g_arrm[mtile * 32];

    const int cc = lane & 3;
    const int hbash = ntile * 32 + wn * 8 + (cc >> 1);
    const int mg0 = m0 + (lane >> 2);                // rows mg0 + ms*16 + mh*8

    // ---- fill W slice (n128 x k256, pitch 512B) into U slot, compute pre ----
    {
        char *p = sm;
#pragma unroll
        for (int i = 0; i < 32; ++i) {
            int u = tid + NTHR * i, n = u >> 5, kg = u & 31;
            uint32_t d = n * 512 + ((kg * 16) ^ ((n & 7) << 4));
            *(uint4 *)(p + SO_U + d) =
                *(const uint4 *)(g_Wf + (size_t)(ntile * 128 + n) * 256 + kg * 8);
        }
    }
    __syncthreads();

    float C[8][4];
#pragma unroll
    for (int a = 0; a < 8; ++a)
#pragma unroll
        for (int r = 0; r < 4; ++r) C[a][r] = 0.0f;
    run_pre(g_x0h, g_x0l, m0, smb, tid, lane, wn, C);

    float pre[8][4];
#pragma unroll
    for (int ms = 0; ms < 2; ++ms)
#pragma unroll
        for (int nb = 0; nb < 4; ++nb)
#pragma unroll
            for (int r = 0; r < 4; ++r) {
                int gate = (cc * 2 + (r & 1)) & 3;
                int hg = ntile * 32 + wn * 8 + nb * 2 + (cc >> 1);
                pre[ms * 4 + nb][r] = C[ms * 4 + nb][r] + __ldg(Wb + gate * 512 + hg);
            }
    __syncthreads();

    // ---- fill U resident (n128 x k512, pitch 1024B, fp16, 128KB) ----
    {
        char *p = sm;
#pragma unroll
        for (int i = 0; i < 64; ++i) {
            int u = tid + NTHR * i, n = u >> 6, kg = u & 63;
            uint32_t d = n * 1024 + ((kg * 16) ^ ((n & 7) << 4));
            *(uint4 *)(p + SO_U + d) =
                *(const uint4 *)(g_Uf + (size_t)(ntile * 128 + n) * 512 + kg * 8);
        }
    }
    __syncthreads();

    // ---- per-thread cell states (8 cells: [p][ms][mh]); fp32 resident ----
    float cs[2][2][2], hs[2][2][2];
#pragma unroll
    for (int p = 0; p < 2; ++p) {
        int nb = (lane & 1) ? 2 + p : p;
        int hg = hbash + nb * 2;
#pragma unroll
        for (int ms = 0; ms < 2; ++ms)
#pragma unroll
            for (int mh = 0; mh < 2; ++mh) {
                int mg = mg0 + ms * 16 + mh * 8;
                cs[p][ms][mh] = __ldg(c0in + (size_t)mg * 512 + hg);
                hs[p][ms][mh] = __ldg(h0in + (size_t)mg * 512 + hg);
            }
    }

    // ---- time loop: per-mtile monotone-counter barrier (16 CTAs/group) ----
    for (int t = 0; t < TT; ++t) {
        const __half *gh = g_ah[t & 1];
#pragma unroll
        for (int a = 0; a < 8; ++a)
#pragma unroll
            for (int r = 0; r < 4; ++r) C[a][r] = 0.0f;

        __syncthreads();   // A-buffer reuse guard
        fill_chunk(gh, HH, m0, 0, smb, tid);
        CP_COMMIT;
        fill_chunk(gh, HH, m0, 1, smb, tid);
        CP_COMMIT;
        asm volatile("cp.async.wait_group 1;" ::: "memory");
        __syncthreads();
        compute_chunk(smb, smb, 0, lane, wn, C);
        asm volatile("cp.async.wait_group 0;" ::: "memory");
        __syncthreads();
        compute_chunk(smb + AB1, smb, 1, lane, wn, C);

        const int bs = __ldg(bsz + t);

        // gate sums = C + pre; exchange complementary gate pairs with lane^1
        float own[2][2][4], R[2][2][4];
#pragma unroll
        for (int p = 0; p < 2; ++p)
#pragma unroll
            for (int ms = 0; ms < 2; ++ms)
#pragma unroll
                for (int r = 0; r < 4; ++r) {
                    float lo2 = C[ms * 4 + p][r] + pre[ms * 4 + p][r];
                    float hi2 = C[ms * 4 + 2 + p][r] + pre[ms * 4 + 2 + p][r];
                    own[p][ms][r] = (lane & 1) ? hi2 : lo2;
                    float send = (lane & 1) ? lo2 : hi2;
                    R[p][ms][r] = __shfl_xor_sync(0xffffffffu, send, 1);
                }

        float o4[2][2][2];
#pragma unroll
        for (int p = 0; p < 2; ++p)
#pragma unroll
            for (int ms = 0; ms < 2; ++ms)
#pragma unroll
                for (int mh = 0; mh < 2; ++mh) {
                    float vi, vf, vg, vo;
                    if (lane & 1) {
                        vg = own[p][ms][mh * 2]; vo = own[p][ms][mh * 2 + 1];
                        vi = R[p][ms][mh * 2];   vf = R[p][ms][mh * 2 + 1];
                    } else {
                        vi = own[p][ms][mh * 2]; vf = own[p][ms][mh * 2 + 1];
                        vg = R[p][ms][mh * 2];   vo = R[p][ms][mh * 2 + 1];
                    }
                    int mg = mg0 + ms * 16 + mh * 8;
                    float cn = sigf(vf) * cs[p][ms][mh] + sigf(vi) * tanhfast(vg);
                    float hn = sigf(vo) * tanhfast(cn);
                    bool act = (mg < bs);
                    o4[p][ms][mh] = act ? hn : 0.0f;
                    if (act) { cs[p][ms][mh] = cn; hs[p][ms][mh] = hn; }
                }

        if (t < TT - 1) {
            // drift on h dims 0,1 (ntile 0, wn 0, nb 0 → even lanes, cc 0 and 2)
            if (ntile == 0 && wn == 0) {
#pragma unroll
                for (int ms = 0; ms < 2; ++ms)
#pragma unroll
                    for (int mh = 0; mh < 2; ++mh) {
                        float mine = hs[0][ms][mh];
                        float oth = __shfl_xor_sync(0xffffffffu, mine, 2);
                        if (!(lane & 1)) {
                            if (cc == 0)
                                hs[0][ms][mh] =
                                    mine + tauv * (1.5f * mine + oth * (1.0f / 1.5f));
                            else if (cc == 2)
                                hs[0][ms][mh] = mine - tauv * (1.5f * oth);
                        }
                    }
            }
            __half *dh = g_ah[(t + 1) & 1];
#pragma unroll
            for (int p = 0; p < 2; ++p) {
                int nb = (lane & 1) ? 2 + p : p;
                int hg = hbash + nb * 2;
#pragma unroll
                for (int ms = 0; ms < 2; ++ms)
#pragma unroll
                    for (int mh = 0; mh < 2; ++mh) {
                        int mg = mg0 + ms * 16 + mh * 8;
                        dh[(size_t)mg * 512 + hg] = __float2half_rn(hs[p][ms][mh]);
                    }
            }
            // release h writes, arrive; overlap out-stores with barrier wait
            __threadfence();
            __syncthreads();
            if (tid == 0) atomicAdd(mybar, 1u);
#pragma unroll
            for (int p = 0; p < 2; ++p) {
                int nb = (lane & 1) ? 2 + p : p;
                int hg = hbash + nb * 2;
#pragma unroll
                for (int ms = 0; ms < 2; ++ms)
#pragma unroll
                    for (int mh = 0; mh < 2; ++mh) {
                        int mg = mg0 + ms * 16 + mh * 8;
                        out[(size_t)t * BH + (size_t)mg * 512 + hg] = o4[p][ms][mh];
                    }
            }
            if (tid == 0) {
                const unsigned tgt = (unsigned)(t + 1) * 16u;
                while (ldacq(mybar) < tgt) {}
            }
            __syncthreads();
        } else {
#pragma unroll
            for (int p = 0; p < 2; ++p) {
                int nb = (lane & 1) ? 2 + p : p;
                int hg = hbash + nb * 2;
#pragma unroll
                for (int ms = 0; ms < 2; ++ms)
#pragma unroll
                    for (int mh = 0; mh < 2; ++mh) {
                        int mg = mg0 + ms * 16 + mh * 8;
                        out[(size_t)t * BH + (size_t)mg * 512 + hg] = o4[p][ms][mh];
                    }
            }
        }
    }

    // ---- final h, c (from fp32 registers) ----
    const size_t ofs = (size_t)TT * BH;
#pragma unroll
    for (int p = 0; p < 2; ++p) {
        int nb = (lane & 1) ? 2 + p : p;
        int hg = hbash + nb * 2;
#pragma unroll
        for (int ms = 0; ms < 2; ++ms)
#pragma unroll
            for (int mh = 0; mh < 2; ++mh) {
                int mg = mg0 + ms * 16 + mh * 8;
                out[ofs + (size_t)mg * 512 + hg] = hs[p][ms][mh];
                out[ofs + BH + (size_t)mg * 512 + hg] = cs[p][ms][mh];
            }
    }
}

extern "C" void kernel_launch(void *const *d_in, const int *in_sizes, int n_in,
                              void *d_out, int out_size)
{
    const float *rnn = (const float *)d_in[0];
    const int *bsz = (const int *)d_in[1];
    const float *h0 = (const float *)d_in[2];
    const float *c0 = (const float *)d_in[3];
    const float *tau = (const float *)d_in[4];
    const float *Ww = (const float *)d_in[5];
    const float *Wb = (const float *)d_in[6];
    const float *Uw = (const float *)d_in[7];
    float *out = (float *)d_out;

    cudaFuncSetAttribute(lstm_mma, cudaFuncAttributeMaxDynamicSharedMemorySize,
                         SMEM_TOT);
    prep_kernel<<<512, 256>>>(rnn, h0, Ww, Uw);
    lstm_mma<<<NCTA, NTHR, SMEM_TOT>>>(bsz, h0, c0, tau, Wb, out);
}